// round 14
// baseline (speedup 1.0000x reference)
#include <cuda_runtime.h>
#include <cuda_bf16.h>
#include <stdint.h>

constexpr int kB  = 32;
constexpr int kL  = 128;
constexpr int kD  = 300;
constexpr int kH  = 1024;
constexpr int kH3 = 3 * kH;
constexpr int kH4 = 4 * kH;
constexpr int kH6 = 6 * kH;
constexpr int MAXM = 2048;

#define REF_NONE  (-1)
#define REF_LEAF  0x40000000

typedef unsigned long long u64;

// ---------------- device scratch ----------------
__device__ float g_X[(size_t)kB * kL * kH4];
__device__ float g_hs[(size_t)kB * kL * kH];
__device__ float g_cs[(size_t)kB * kL * kH];
__device__ float g_nodeh[(size_t)kB * 128 * kH];
__device__ float g_nodec[(size_t)kB * 128 * kH];
__device__ float g_gates[(size_t)MAXM * kH6];     // also holds K-split partials
__device__ float g_hT[2][kH * kB];                // [(k>>2)*128 + b*4 + (k&3)]

__device__ int g_nodeL[kB * 128];
__device__ int g_nodeR[kB * 128];
__device__ int g_nodeX[kB * 128];
__device__ int g_nodeLvl[kB * 128];
__device__ int g_nNodes[kB];
__device__ int g_root[kB];
__device__ int g_lvlList[kB * 128];
__device__ int g_lvlOff[132];
__device__ int g_maxLvl;

__device__ unsigned g_barCount = 0;
__device__ unsigned g_barGen   = 0;

// ---------------- helpers ----------------
__device__ __forceinline__ float sigm(float x) { return 1.0f / (1.0f + expf(-x)); }

__device__ __forceinline__ void gridBarrier(unsigned &gen) {
    __syncthreads();
    if (threadIdx.x == 0) {
        __threadfence();
        if (atomicAdd(&g_barCount, 1u) == gridDim.x - 1u) {
            g_barCount = 0;
            __threadfence();
            atomicExch(&g_barGen, gen + 1u);
        } else {
            while (*((volatile unsigned *)&g_barGen) < gen + 1u) __nanosleep(32);
        }
    }
    gen++;
    __syncthreads();
}

__device__ __forceinline__ u64 packdup(float x) {
    u64 d; unsigned u = __float_as_uint(x);
    asm("mov.b64 %0, {%1, %1};" : "=l"(d) : "r"(u));
    return d;
}
__device__ __forceinline__ u64 pack2(float x, float y) {
    u64 d;
    asm("mov.b64 %0, {%1, %2};" : "=l"(d) : "r"(__float_as_uint(x)), "r"(__float_as_uint(y)));
    return d;
}
__device__ __forceinline__ void unpack2(u64 d, float &x, float &y) {
    unsigned a, b;
    asm("mov.b64 {%0, %1}, %2;" : "=r"(a), "=r"(b) : "l"(d));
    x = __uint_as_float(a); y = __uint_as_float(b);
}
__device__ __forceinline__ void ffma2(u64 &d, u64 a, u64 b) {
    asm("fma.rn.f32x2 %0, %1, %2, %0;" : "+l"(d) : "l"(a), "l"(b));
}

// L1-safe reads (each node h/c written exactly once, first read strictly after)
__device__ __forceinline__ float h_ofg(int ref, int b, int jj) {
    if (ref < 0) return 0.0f;
    if (ref & REF_LEAF) return __ldg(&g_hs[((size_t)(b * kL + (ref & 0xFFFF))) * kH + jj]);
    return __ldg(&g_nodeh[((size_t)(b * 128 + ref)) * kH + jj]);
}
__device__ __forceinline__ float c_ofg(int ref, int b, int jj) {
    if (ref < 0) return 0.0f;
    if (ref & REF_LEAF) return __ldg(&g_cs[((size_t)(b * kL + (ref & 0xFFFF))) * kH + jj]);
    return __ldg(&g_nodec[((size_t)(b * 128 + ref)) * kH + jj]);
}

// ------------- f32x2 GEMM: C[M,N] = A(MxK) @ B(NxK)^T, optional K-split -------------
// 256 threads. BN=128, BK=32. N-PAIRED accumulators: acc[row][colpair].
// A smem is pre-duplicated u64 (packdup at store); B smem natural floats read at the
// PROVEN conflict-free tx*4 / 64+tx*4 float4 addresses, reinterpreted as ulonglong2
// natural column pairs. Inner loop per kk: 4 LDS.128 + TM*4 FFMA2, ZERO MOVs.
// If GATHER, A(row,k) gathered from the tree level (lvlOff).
// K-split: tile index selects ks; partial outputs at C + ks*partStride.
// CALLER guarantees partStride rows >= max cnt for the ksplit tier.
template <int BM, bool GATHER>
__device__ void gemm2(const float *__restrict__ A, int lda, int M, int lvlOff,
                      const float *__restrict__ Bw, int ldb, int N, int K,
                      int ksplit, size_t partStride,
                      float *__restrict__ C, int ldc,
                      const float *__restrict__ bias1,
                      const float *__restrict__ bias2, float *sm) {
    constexpr int BK = 32, BN = 128;
    constexpr int TM = BM / 16;
    constexpr int ALD2 = BM + 2;                  // u64 stride per kk row
    u64 *Ad = (u64 *)sm;                          // [2][BK][ALD2] u64, dup'd A
    float *Bs = sm + 2 * BK * ALD2 * 2;           // [2][BK][132] float
    const int tid = threadIdx.x;
    const int ty = tid >> 4, tx = tid & 15;
    const int tilesM = (M + BM - 1) / BM;
    const int tilesN = N / BN;
    const int tilesMN = tilesM * tilesN;
    const int kLen = K / ksplit;
    const int nk = (kLen + BK - 1) / BK;
    const int total = tilesMN * ksplit;

    for (int t = blockIdx.x; t < total; t += gridDim.x) {
        const int ks = t / tilesMN;
        const int tmn = t - ks * tilesMN;
        const int tm = tmn % tilesM, tn = tmn / tilesM;
        const int m0 = tm * BM, n0 = tn * BN;
        const int kBase = ks * kLen;
        const int kEnd = (kBase + kLen < K) ? (kBase + kLen) : K;
        float *Cp = C + (size_t)ks * partStride;
        u64 acc[TM][4];
#pragma unroll
        for (int p = 0; p < TM; p++)
#pragma unroll
            for (int q = 0; q < 4; q++) acc[p][q] = 0ULL;

        auto load = [&](int buf, int k0) {
            if (GATHER) {
#pragma unroll
                for (int i = 0; i < BM / 8; i++) {
                    int idx = tid + i * 256;
                    int kk = idx & 31, m = idx >> 5;
                    int row = m0 + m, k = kBase + k0 + kk;
                    float v = 0.0f;
                    if (row < M && k < kEnd) {
                        int e = __ldg(&g_lvlList[lvlOff + row]);
                        int bb = e >> 8, nd = e & 255;
                        int seg = k >> 10, jj = k & 1023;
                        if (seg == 1) {
                            int x = __ldg(&g_nodeX[bb * 128 + nd]);
                            v = __ldg(&g_hs[(size_t)(bb * kL + x) * kH + jj]);
                        } else {
                            int ref = __ldg(seg == 0 ? &g_nodeL[bb * 128 + nd]
                                                     : &g_nodeR[bb * 128 + nd]);
                            v = h_ofg(ref, bb, jj);
                        }
                    }
                    Ad[(buf * BK + kk) * ALD2 + m] = packdup(v);
                }
            } else {
                // dense A: float4 along k, scatter-dup to 4 kk rows
#pragma unroll
                for (int i = 0; i < BM / 32; i++) {
                    int idx = tid + i * 256;
                    int kq = idx & 7, m = idx >> 3;
                    int row = m0 + m, k = kBase + k0 + kq * 4;
                    float4 v = make_float4(0.f, 0.f, 0.f, 0.f);
                    if (row < M && k < kEnd)
                        v = __ldg((const float4 *)(A + (size_t)row * lda + k));
                    u64 *dst = &Ad[(buf * BK + kq * 4) * ALD2 + m];
                    dst[0]        = packdup(v.x);
                    dst[ALD2]     = packdup(v.y);
                    dst[2 * ALD2] = packdup(v.z);
                    dst[3 * ALD2] = packdup(v.w);
                }
            }
#pragma unroll
            for (int i = 0; i < 16; i++) {
                int idx = tid + i * 256;
                int kk = idx & 31, n = idx >> 5;
                int k = kBase + k0 + kk;
                float v = (k < kEnd) ? __ldg(Bw + (size_t)(n0 + n) * ldb + k) : 0.0f;
                Bs[(buf * BK + kk) * 132 + n] = v;
            }
        };

        load(0, 0);
        __syncthreads();
        for (int kt = 0; kt < nk; kt++) {
            int buf = kt & 1;
            if (kt + 1 < nk) load(buf ^ 1, (kt + 1) * BK);
#pragma unroll
            for (int kk = 0; kk < BK; kk++) {
                // A: dup'd u64s, 2-address broadcast per warp
                const u64 *Ar = &Ad[(buf * BK + kk) * ALD2 + ty * TM];
                u64 a2[TM];
                if constexpr (TM == 4) {
                    ulonglong2 t0 = *(const ulonglong2 *)Ar;
                    ulonglong2 t1 = *(const ulonglong2 *)(Ar + 2);
                    a2[0] = t0.x; a2[1] = t0.y; a2[2] = t1.x; a2[3] = t1.y;
                } else {
                    ulonglong2 t0 = *(const ulonglong2 *)Ar;
                    a2[0] = t0.x; a2[1] = t0.y;
                }
                // B: natural adjacent-column pairs at the proven tx*4 addresses
                const float *Brow = &Bs[(buf * BK + kk) * 132];
                ulonglong2 bb0 = *(const ulonglong2 *)(Brow + tx * 4);
                ulonglong2 bb1 = *(const ulonglong2 *)(Brow + 64 + tx * 4);
                u64 b2[4] = {bb0.x, bb0.y, bb1.x, bb1.y};
#pragma unroll
                for (int p = 0; p < TM; p++)
#pragma unroll
                    for (int q = 0; q < 4; q++) ffma2(acc[p][q], a2[p], b2[q]);
            }
            __syncthreads();
        }
#pragma unroll
        for (int p = 0; p < TM; p++) {
            int r = m0 + ty * TM + p;
            if (r < M) {
#pragma unroll
                for (int q = 0; q < 4; q++) {
                    float x, y; unpack2(acc[p][q], x, y);
                    int col = n0 + ((q < 2) ? (tx * 4 + 2 * q) : (64 + tx * 4 + 2 * (q - 2)));
                    float bx = 0.0f, by = 0.0f;
                    if (bias1) { bx += __ldg(bias1 + col); by += __ldg(bias1 + col + 1); }
                    if (bias2) { bx += __ldg(bias2 + col); by += __ldg(bias2 + col + 1); }
                    __stcg(Cp + (size_t)r * ldc + col, x + bx);
                    __stcg(Cp + (size_t)r * ldc + col + 1, y + by);
                }
            }
        }
    }
}

// ---------------- tree kernel: warp per batch, stacks in smem ----------------
__global__ __launch_bounds__(1024) void tree_kernel(const int *__restrict__ words,
                                                    const int *__restrict__ length) {
    extern __shared__ char tsm[];
    int wid = threadIdx.x >> 5, lane = threadIdx.x & 31;
    if (wid < kB) {
        int b = wid;
        char *wb = tsm + wid * 1920;
        short *ss   = (short *)(wb);
        short *se   = (short *)(wb + 256);
        short *spos = (short *)(wb + 512);
        signed char *sst = (signed char *)(wb + 768);
        int *sleft  = (int *)(wb + 896);
        int *lvl    = (int *)(wb + 1408);

        int dfv[4];
#pragma unroll
        for (int i = 0; i < 4; i++) dfv[i] = words[b * kL + lane + 32 * i] % 1000;
        int n = length[b];

        auto argminSeg = [&](int s, int e) -> int {
            int best = 0x7FFFFFFF;
#pragma unroll
            for (int i = 0; i < 4; i++) {
                int p = lane + 32 * i;
                if (p >= s && p < e) {
                    int pk = (dfv[i] << 7) | p;
                    if (pk < best) best = pk;
                }
            }
#pragma unroll
            for (int o = 16; o; o >>= 1) {
                int ot = __shfl_xor_sync(0xffffffffu, best, o);
                if (ot < best) best = ot;
            }
            return best & 127;
        };

        int nn = 0, root;
        if (n <= 0) root = REF_NONE;
        else if (n == 1) root = REF_LEAF | 0;
        else {
            int sp = 0;
            ss[0] = 0; se[0] = (short)n; sst[0] = 0; sp = 1;
            int ret = 0;
            bool returning = false;
            while (sp > 0) {
                int top = sp - 1;
                if (returning) {
                    if (sst[top] == 1) {
                        sleft[top] = ret; sst[top] = 2; returning = false;
                    } else {
                        int Lr = sleft[top], Rr = ret, x = spos[top];
                        int ll = (Lr >= 0 && !(Lr & REF_LEAF)) ? lvl[Lr] : 0;
                        int rl = (Rr >= 0 && !(Rr & REF_LEAF)) ? lvl[Rr] : 0;
                        lvl[nn] = 1 + (ll > rl ? ll : rl);
                        if (lane == 0) {
                            g_nodeL[b * 128 + nn] = Lr;
                            g_nodeR[b * 128 + nn] = Rr;
                            g_nodeX[b * 128 + nn] = x;
                            g_nodeLvl[b * 128 + nn] = lvl[nn];
                        }
                        ret = nn; nn++; sp--;
                        continue;
                    }
                }
                if (sst[top] == 0) {
                    int s = ss[top], e = se[top];
                    int bp = argminSeg(s, e);
                    spos[top] = (short)bp;
                    if (bp == s)          { sleft[top] = REF_NONE;     sst[top] = 2; }
                    else if (bp == s + 1) { sleft[top] = REF_LEAF | s; sst[top] = 2; }
                    else {
                        sst[top] = 1;
                        ss[sp] = (short)s; se[sp] = (short)bp; sst[sp] = 0; sp++;
                        continue;
                    }
                }
                if (sst[top] == 2) {
                    int rs = spos[top] + 1, e = se[top];
                    int Rr;
                    if (rs == e)          Rr = REF_NONE;
                    else if (rs + 1 == e) Rr = REF_LEAF | rs;
                    else {
                        sst[top] = 3;
                        ss[sp] = (short)rs; se[sp] = (short)e; sst[sp] = 0; sp++;
                        continue;
                    }
                    int Lr = sleft[top], x = spos[top];
                    int ll = (Lr >= 0 && !(Lr & REF_LEAF)) ? lvl[Lr] : 0;
                    int rl = (Rr >= 0 && !(Rr & REF_LEAF)) ? lvl[Rr] : 0;
                    lvl[nn] = 1 + (ll > rl ? ll : rl);
                    if (lane == 0) {
                        g_nodeL[b * 128 + nn] = Lr;
                        g_nodeR[b * 128 + nn] = Rr;
                        g_nodeX[b * 128 + nn] = x;
                        g_nodeLvl[b * 128 + nn] = lvl[nn];
                    }
                    ret = nn; nn++; sp--;
                    returning = true;
                }
            }
            root = ret;
        }
        if (lane == 0) { g_root[b] = root; g_nNodes[b] = nn; }
    }
    __syncthreads();
    if (threadIdx.x == 0) {
        int cnt[130];
        for (int i = 0; i < 130; i++) cnt[i] = 0;
        int mx = 0;
        for (int bb = 0; bb < kB; bb++) {
            int nn = g_nNodes[bb];
            for (int i = 0; i < nn; i++) {
                int lv = g_nodeLvl[bb * 128 + i];
                cnt[lv]++;
                if (lv > mx) mx = lv;
            }
        }
        int run = 0;
        for (int lv = 1; lv <= mx; lv++) { g_lvlOff[lv] = run; run += cnt[lv]; }
        g_lvlOff[mx + 1] = run;
        int pos[130];
        for (int lv = 1; lv <= mx; lv++) pos[lv] = g_lvlOff[lv];
        for (int bb = 0; bb < kB; bb++) {
            int nn = g_nNodes[bb];
            for (int i = 0; i < nn; i++) {
                int lv = g_nodeLvl[bb * 128 + i];
                g_lvlList[pos[lv]++] = (bb << 8) | i;
            }
        }
        g_maxLvl = mx;
    }
}

// ---------------- X precompute: g_X = emb @ W_ih^T + b_ih + b_hh ----------------
__global__ __launch_bounds__(256, 3) void x_kernel(const float *__restrict__ emb,
                                                   const float *__restrict__ Wih,
                                                   const float *__restrict__ bih,
                                                   const float *__restrict__ bhh) {
    extern __shared__ float xsm[];
    gemm2<64, false>(emb, kD, kB * kL, 0, Wih, kD, kH4, kD, 1, 0,
                     g_X, kH4, bih, bhh, xsm);
}

// ---------------- LSTM kernel (weight-stationary, deep LDG pipeline) ----------------
__global__ __launch_bounds__(256, 1) void lstm_kernel(const float *__restrict__ Whh) {
    extern __shared__ float sm[];
    unsigned gen = *((volatile unsigned *)&g_barGen);
    const int tid = threadIdx.x;
    const int bk = blockIdx.x;

    int nj = 1024 - bk * 7;
    if (nj > 7) nj = 7;
    if (nj < 0) nj = 0;
    for (int idx = tid; idx < nj * 4096; idx += 256)
        sm[idx] = __ldg(&Whh[((size_t)((idx >> 10) & 3) * kH + bk * 7 + (idx >> 12)) * kH
                             + (idx & 1023)]);
    __syncthreads();

    const int s = tid >> 5, b = tid & 31;
    const bool active = (s < nj);
    const int j = bk * 7 + s;
    const float *Ws = sm + s * 4096;
    float cprev = 0.0f;

    for (int t = 0; t < kL; t++) {
        float av[4] = {0.f, 0.f, 0.f, 0.f};
        if (active) {
            if (t > 0) {
                u64 accp[4] = {0ULL, 0ULL, 0ULL, 0ULL};
                const float *hTp = (const float *)g_hT[(t - 1) & 1];
#pragma unroll 16
                for (int kq = 0; kq < 256; kq++) {
                    float4 h4 = __ldcg((const float4 *)(hTp + kq * 128 + b * 4));
                    u64 alo = pack2(h4.x, h4.y);
                    u64 ahi = pack2(h4.z, h4.w);
#pragma unroll
                    for (int g = 0; g < 4; g++) {
                        ulonglong2 w = *(const ulonglong2 *)(Ws + g * 1024 + kq * 4);
                        ffma2(accp[g], alo, w.x);
                        ffma2(accp[g], ahi, w.y);
                    }
                }
#pragma unroll
                for (int g = 0; g < 4; g++) {
                    float x, y; unpack2(accp[g], x, y);
                    av[g] = x + y;
                }
            }
            const float *Xr = g_X + ((size_t)(b * kL + t)) * kH4;
            float gi = av[0] + __ldg(Xr + j);
            float gf = av[1] + __ldg(Xr + kH + j);
            float gg = av[2] + __ldg(Xr + 2 * kH + j);
            float go = av[3] + __ldg(Xr + 3 * kH + j);
            float c = sigm(gf) * cprev + sigm(gi) * tanhf(gg);
            float h = sigm(go) * tanhf(c);
            cprev = c;
            __stcg(&g_hs[((size_t)(b * kL + t)) * kH + j], h);
            __stcg(&g_cs[((size_t)(b * kL + t)) * kH + j], c);
            __stcg(&g_hT[t & 1][(j >> 2) * 128 + b * 4 + (j & 3)], h);
        }
        gridBarrier(gen);
    }
}

// ---------------- compose kernel: 444 persistent blocks, 3/SM ----------------
__global__ __launch_bounds__(256, 3) void compose_kernel(const float *__restrict__ Wcomp,
                                                         const float *__restrict__ bcomp,
                                                         float *__restrict__ out) {
    extern __shared__ float sm[];
    unsigned gen = *((volatile unsigned *)&g_barGen);
    const int tid = threadIdx.x;
    const int gtid = blockIdx.x * 256 + tid;
    const int gsz = gridDim.x * 256;
    const int maxLvl = g_maxLvl;

    for (int lvl = 1; lvl <= maxLvl; lvl++) {
        const int off = g_lvlOff[lvl];
        const int cnt = g_lvlOff[lvl + 1] - off;
        // per-ksplit non-overlapping partial stride: (MAXM/ksplit) rows each.
        // ks2 -> 1024 rows (cnt<=384), ks4 -> 512 (cnt<=128), ks8 -> 256 (cnt<=32).
        int ksplit;
        if (cnt > 384)       ksplit = 1;
        else if (cnt > 128)  ksplit = 2;
        else if (cnt > 32)   ksplit = 4;
        else                 ksplit = 8;
        const size_t partStride = (size_t)(MAXM / ksplit) * kH6;

        if (ksplit == 8)
            gemm2<32, true>(nullptr, 0, cnt, off, Wcomp, kH3, kH6, kH3,
                            8, partStride, g_gates, kH6, nullptr, nullptr, sm);
        else if (ksplit == 4)
            gemm2<64, true>(nullptr, 0, cnt, off, Wcomp, kH3, kH6, kH3,
                            4, partStride, g_gates, kH6, nullptr, nullptr, sm);
        else if (ksplit == 2)
            gemm2<64, true>(nullptr, 0, cnt, off, Wcomp, kH3, kH6, kH3,
                            2, partStride, g_gates, kH6, nullptr, nullptr, sm);
        else
            gemm2<64, true>(nullptr, 0, cnt, off, Wcomp, kH3, kH6, kH3,
                            1, partStride, g_gates, kH6, nullptr, nullptr, sm);
        gridBarrier(gen);

        // epilogue: sum K-split partials + bias, gate nonlinearity, cell update
        for (int idx = gtid; idx < cnt * kH; idx += gsz) {
            int i = idx >> 10, jj = idx & 1023;
            int e = g_lvlList[off + i];
            int bb = e >> 8, nd = e & 255;
            const float *gp = g_gates + (size_t)i * kH6 + jj;
            float a0 = __ldg(bcomp + jj);
            float a1 = __ldg(bcomp + kH + jj);
            float a2 = __ldg(bcomp + 2 * kH + jj);
            float a3 = __ldg(bcomp + 3 * kH + jj);
            float a4 = __ldg(bcomp + 4 * kH + jj);
            float a5 = __ldg(bcomp + 5 * kH + jj);
            for (int p = 0; p < ksplit; p++) {
                const float *pp = gp + (size_t)p * partStride;
                a0 += __ldcg(pp);
                a1 += __ldcg(pp + kH);
                a2 += __ldcg(pp + 2 * kH);
                a3 += __ldcg(pp + 3 * kH);
                a4 += __ldcg(pp + 4 * kH);
                a5 += __ldcg(pp + 5 * kH);
            }
            int rl = g_nodeL[bb * 128 + nd];
            int rr = g_nodeR[bb * 128 + nd];
            int x  = g_nodeX[bb * 128 + nd];
            float cl = c_ofg(rl, bb, jj);
            float cr = c_ofg(rr, bb, jj);
            float cx = __ldg(&g_cs[(size_t)(bb * kL + x) * kH + jj]);
            float c = sigm(a0) * tanhf(a4) + sigm(a1) * cl + sigm(a2) * cx + sigm(a3) * cr;
            float h = sigm(a5) * tanhf(c);
            __stcg(&g_nodeh[(size_t)(bb * 128 + nd) * kH + jj], h);
            __stcg(&g_nodec[(size_t)(bb * 128 + nd) * kH + jj], c);
        }
        gridBarrier(gen);
    }

    // output: h then c of each batch root
    for (int idx = gtid; idx < kB * kH; idx += gsz) {
        int bb = idx >> 10, jj = idx & 1023;
        int r = g_root[bb];
        out[idx]           = h_ofg(r, bb, jj);
        out[kB * kH + idx] = c_ofg(r, bb, jj);
    }
}

// ---------------- launch ----------------
extern "C" void kernel_launch(void *const *d_in, const int *in_sizes, int n_in,
                              void *d_out, int out_size) {
    (void)in_sizes; (void)n_in; (void)out_size;
    const float *emb   = (const float *)d_in[0];
    const float *Wih   = (const float *)d_in[1];
    const float *Whh   = (const float *)d_in[2];
    const float *bih   = (const float *)d_in[3];
    const float *bhh   = (const float *)d_in[4];
    const float *Wcomp = (const float *)d_in[5];
    const float *bcomp = (const float *)d_in[6];
    const int *words   = (const int *)d_in[7];
    const int *len     = (const int *)d_in[8];
    float *out = (float *)d_out;

    // smem gemm2 BM=64: A dup 2*32*66*8=33792 + B 2*32*132*4=33792 = 67584 B
    // 3 blocks/SM: 202.75 KB smem/SM (< 228 KB), regs capped at 80 by launch bounds.
    static bool attrDone = false;
    if (!attrDone) {
        cudaFuncSetAttribute(tree_kernel, cudaFuncAttributeMaxDynamicSharedMemorySize, 61440);
        cudaFuncSetAttribute(x_kernel, cudaFuncAttributeMaxDynamicSharedMemorySize, 67584);
        cudaFuncSetAttribute(lstm_kernel, cudaFuncAttributeMaxDynamicSharedMemorySize, 114688);
        cudaFuncSetAttribute(compose_kernel, cudaFuncAttributeMaxDynamicSharedMemorySize, 67584);
        attrDone = true;
    }

    tree_kernel<<<1, 1024, 61440>>>(words, len);
    x_kernel<<<2048, 256, 67584>>>(emb, Wih, bih, bhh);
    lstm_kernel<<<148, 256, 114688>>>(Whh);
    compose_kernel<<<444, 256, 67584>>>(Wcomp, bcomp, out);
}

// round 15
// speedup vs baseline: 1.2556x; 1.2556x over previous
#include <cuda_runtime.h>
#include <cuda_bf16.h>
#include <stdint.h>

constexpr int kB  = 32;
constexpr int kL  = 128;
constexpr int kD  = 300;
constexpr int kH  = 1024;
constexpr int kH3 = 3 * kH;
constexpr int kH4 = 4 * kH;
constexpr int kH6 = 6 * kH;
constexpr int MAXM = 2048;

#define REF_NONE  (-1)
#define REF_LEAF  0x40000000

typedef unsigned long long u64;

// ---------------- device scratch ----------------
__device__ float g_X[(size_t)kB * kL * kH4];
__device__ float g_hs[(size_t)kB * kL * kH];
__device__ float g_cs[(size_t)kB * kL * kH];
__device__ float g_nodeh[(size_t)kB * 128 * kH];
__device__ float g_nodec[(size_t)kB * 128 * kH];
__device__ float g_gates[(size_t)MAXM * kH6];     // also holds K-split partials
__device__ float g_hT[2][kH * kB];                // [(k>>2)*128 + b*4 + (k&3)]

__device__ int g_nodeL[kB * 128];
__device__ int g_nodeR[kB * 128];
__device__ int g_nodeX[kB * 128];
__device__ int g_nodeLvl[kB * 128];
__device__ int g_nNodes[kB];
__device__ int g_root[kB];
__device__ int g_lvlList[kB * 128];
__device__ int g_lvlOff[132];
__device__ int g_maxLvl;

__device__ unsigned g_barCount = 0;
__device__ unsigned g_barGen   = 0;

// ---------------- helpers ----------------
__device__ __forceinline__ float sigm(float x) { return 1.0f / (1.0f + expf(-x)); }

__device__ __forceinline__ void gridBarrier(unsigned &gen) {
    __syncthreads();
    if (threadIdx.x == 0) {
        __threadfence();
        if (atomicAdd(&g_barCount, 1u) == gridDim.x - 1u) {
            g_barCount = 0;
            __threadfence();
            atomicExch(&g_barGen, gen + 1u);
        } else {
            while (*((volatile unsigned *)&g_barGen) < gen + 1u) __nanosleep(32);
        }
    }
    gen++;
    __syncthreads();
}

__device__ __forceinline__ u64 packdup(float x) {
    u64 d; unsigned u = __float_as_uint(x);
    asm("mov.b64 %0, {%1, %1};" : "=l"(d) : "r"(u));
    return d;
}
__device__ __forceinline__ u64 pack2(float x, float y) {
    u64 d;
    asm("mov.b64 %0, {%1, %2};" : "=l"(d) : "r"(__float_as_uint(x)), "r"(__float_as_uint(y)));
    return d;
}
__device__ __forceinline__ void unpack2(u64 d, float &x, float &y) {
    unsigned a, b;
    asm("mov.b64 {%0, %1}, %2;" : "=r"(a), "=r"(b) : "l"(d));
    x = __uint_as_float(a); y = __uint_as_float(b);
}
__device__ __forceinline__ void ffma2(u64 &d, u64 a, u64 b) {
    asm("fma.rn.f32x2 %0, %1, %2, %0;" : "+l"(d) : "l"(a), "l"(b));
}

// L1-safe reads (each node h/c written exactly once, first read strictly after)
__device__ __forceinline__ float h_ofg(int ref, int b, int jj) {
    if (ref < 0) return 0.0f;
    if (ref & REF_LEAF) return __ldg(&g_hs[((size_t)(b * kL + (ref & 0xFFFF))) * kH + jj]);
    return __ldg(&g_nodeh[((size_t)(b * 128 + ref)) * kH + jj]);
}
__device__ __forceinline__ float c_ofg(int ref, int b, int jj) {
    if (ref < 0) return 0.0f;
    if (ref & REF_LEAF) return __ldg(&g_cs[((size_t)(b * kL + (ref & 0xFFFF))) * kH + jj]);
    return __ldg(&g_nodec[((size_t)(b * 128 + ref)) * kH + jj]);
}

// ------------- f32x2 GEMM: C[M,N] = A(MxK) @ B(NxK)^T, optional K-split -------------
// 256 threads. BN=128, BK=32, thread tile TM x 8 with the 8 columns split as
// {tx*4..tx*4+3} and {64+tx*4..} -> conflict-free LDS.128 B reads (R12-proven loop).
// If GATHER: per-tile row base-pointer table (rowPtr[BM][3], one per k-segment) is
// built ONCE per tile, so the per-chunk A load is a pure float4 LDG — the dependent
// lvlList->node->h chain is hoisted out of the k-loop (was re-run every BK chunk).
// K-split: tile index selects ks; partial outputs at C + ks*partStride.
// CALLER guarantees partStride rows >= max cnt for the ksplit tier.
template <int BM, bool GATHER>
__device__ void gemm2(const float *__restrict__ A, int lda, int M, int lvlOff,
                      const float *__restrict__ Bw, int ldb, int N, int K,
                      int ksplit, size_t partStride,
                      float *__restrict__ C, int ldc,
                      const float *__restrict__ bias1,
                      const float *__restrict__ bias2, float *sm) {
    constexpr int BK = 32, BN = 128, TN = 8;
    constexpr int TM = BM / 16;
    constexpr int NP = TM / 2;
    constexpr int ALD = BM + 4;
    float *As = sm;                          // [2][BK][ALD]
    float *Bs = sm + 2 * BK * ALD;           // [2][BK][132]
    u64 *rowPtr = (u64 *)(sm + 2 * BK * ALD + 2 * BK * 132);  // [BM][3]
    const int tid = threadIdx.x;
    const int ty = tid >> 4, tx = tid & 15;
    const int tilesM = (M + BM - 1) / BM;
    const int tilesN = N / BN;
    const int tilesMN = tilesM * tilesN;
    const int kLen = K / ksplit;
    const int nk = (kLen + BK - 1) / BK;
    const int total = tilesMN * ksplit;

    for (int t = blockIdx.x; t < total; t += gridDim.x) {
        const int ks = t / tilesMN;
        const int tmn = t - ks * tilesMN;
        const int tm = tmn % tilesM, tn = tmn / tilesM;
        const int m0 = tm * BM, n0 = tn * BN;
        const int kBase = ks * kLen;
        const int kEnd = (kBase + kLen < K) ? (kBase + kLen) : K;
        float *Cp = C + (size_t)ks * partStride;
        u64 acc[NP][TN];
#pragma unroll
        for (int p = 0; p < NP; p++)
#pragma unroll
            for (int j = 0; j < TN; j++) acc[p][j] = 0ULL;

        if (GATHER) {
            // build per-row segment base pointers once per tile
            for (int idx = tid; idx < BM * 3; idx += 256) {
                int m = idx / 3, seg = idx - m * 3;
                int row = m0 + m;
                u64 p = 0;
                if (row < M) {
                    int e = __ldg(&g_lvlList[lvlOff + row]);
                    int bb = e >> 8, nd = e & 255;
                    if (seg == 1) {
                        int x = __ldg(&g_nodeX[bb * 128 + nd]);
                        p = (u64)(uintptr_t)&g_hs[(size_t)(bb * kL + x) * kH];
                    } else {
                        int ref = __ldg(seg == 0 ? &g_nodeL[bb * 128 + nd]
                                                 : &g_nodeR[bb * 128 + nd]);
                        if (ref >= 0) {
                            p = (ref & REF_LEAF)
                                ? (u64)(uintptr_t)&g_hs[(size_t)(bb * kL + (ref & 0xFFFF)) * kH]
                                : (u64)(uintptr_t)&g_nodeh[(size_t)(bb * 128 + ref) * kH];
                        }
                    }
                }
                rowPtr[idx] = p;
            }
            __syncthreads();
        }

        auto load = [&](int buf, int k0) {
            if (GATHER) {
                // float4 gather via precomputed pointers (no index chain)
#pragma unroll
                for (int i = 0; i < BM / 32; i++) {
                    int idx = tid + i * 256;
                    int kq = idx & 7, m = idx >> 3;
                    int k = kBase + k0 + kq * 4;
                    int seg = k >> 10;
                    const float *p = (const float *)(uintptr_t)rowPtr[m * 3 + seg];
                    float4 v = make_float4(0.f, 0.f, 0.f, 0.f);
                    if (p && k < kEnd)
                        v = __ldg((const float4 *)(p + (k & 1023)));
                    float *dst = &As[(buf * BK + kq * 4) * ALD + m];
                    dst[0]       = v.x;
                    dst[ALD]     = v.y;
                    dst[2 * ALD] = v.z;
                    dst[3 * ALD] = v.w;
                }
            } else {
#pragma unroll
                for (int i = 0; i < BM / 8; i++) {
                    int idx = tid + i * 256;
                    int kk = idx & 31, m = idx >> 5;
                    int row = m0 + m, k = kBase + k0 + kk;
                    float v = 0.0f;
                    if (row < M && k < kEnd)
                        v = __ldg(A + (size_t)row * lda + k);
                    As[(buf * BK + kk) * ALD + m] = v;
                }
            }
#pragma unroll
            for (int i = 0; i < 16; i++) {
                int idx = tid + i * 256;
                int kk = idx & 31, n = idx >> 5;
                int k = kBase + k0 + kk;
                float v = (k < kEnd) ? __ldg(Bw + (size_t)(n0 + n) * ldb + k) : 0.0f;
                Bs[(buf * BK + kk) * 132 + n] = v;
            }
        };

        load(0, 0);
        __syncthreads();
        for (int kt = 0; kt < nk; kt++) {
            int buf = kt & 1;
            if (kt + 1 < nk) load(buf ^ 1, (kt + 1) * BK);
#pragma unroll
            for (int kk = 0; kk < BK; kk++) {
                const float *Ar = &As[(buf * BK + kk) * ALD + ty * TM];
                u64 a2[NP];
                if constexpr (NP == 4) {
                    ulonglong2 t0 = *(const ulonglong2 *)Ar;
                    ulonglong2 t1 = *(const ulonglong2 *)(Ar + 4);
                    a2[0] = t0.x; a2[1] = t0.y; a2[2] = t1.x; a2[3] = t1.y;
                } else if constexpr (NP == 2) {
                    ulonglong2 t0 = *(const ulonglong2 *)Ar;
                    a2[0] = t0.x; a2[1] = t0.y;
                } else {
                    a2[0] = *(const u64 *)Ar;
                }
                // conflict-free B reads: stride-4-word addresses per lane
                const float *Brow = &Bs[(buf * BK + kk) * 132];
                float4 b0 = *(const float4 *)(Brow + tx * 4);
                float4 b1 = *(const float4 *)(Brow + 64 + tx * 4);
                u64 bd[8];
                bd[0] = packdup(b0.x); bd[1] = packdup(b0.y);
                bd[2] = packdup(b0.z); bd[3] = packdup(b0.w);
                bd[4] = packdup(b1.x); bd[5] = packdup(b1.y);
                bd[6] = packdup(b1.z); bd[7] = packdup(b1.w);
#pragma unroll
                for (int p = 0; p < NP; p++)
#pragma unroll
                    for (int j = 0; j < TN; j++) ffma2(acc[p][j], a2[p], bd[j]);
            }
            __syncthreads();
        }
#pragma unroll
        for (int p = 0; p < NP; p++) {
            int r = m0 + ty * TM + 2 * p;
#pragma unroll
            for (int j = 0; j < TN; j++) {
                float x, y; unpack2(acc[p][j], x, y);
                int col = n0 + ((j < 4) ? (tx * 4 + j) : (64 + tx * 4 + (j - 4)));
                float bv = 0.0f;
                if (bias1) bv += __ldg(bias1 + col);
                if (bias2) bv += __ldg(bias2 + col);
                if (r < M)     __stcg(Cp + (size_t)r * ldc + col, x + bv);
                if (r + 1 < M) __stcg(Cp + (size_t)(r + 1) * ldc + col, y + bv);
            }
        }
        if (GATHER) __syncthreads();   // protect rowPtr before next tile rewrites it
    }
}

// ---------------- tree kernel: warp per batch, stacks in smem ----------------
__global__ __launch_bounds__(1024) void tree_kernel(const int *__restrict__ words,
                                                    const int *__restrict__ length) {
    extern __shared__ char tsm[];
    int wid = threadIdx.x >> 5, lane = threadIdx.x & 31;
    if (wid < kB) {
        int b = wid;
        char *wb = tsm + wid * 1920;
        short *ss   = (short *)(wb);
        short *se   = (short *)(wb + 256);
        short *spos = (short *)(wb + 512);
        signed char *sst = (signed char *)(wb + 768);
        int *sleft  = (int *)(wb + 896);
        int *lvl    = (int *)(wb + 1408);

        int dfv[4];
#pragma unroll
        for (int i = 0; i < 4; i++) dfv[i] = words[b * kL + lane + 32 * i] % 1000;
        int n = length[b];

        auto argminSeg = [&](int s, int e) -> int {
            int best = 0x7FFFFFFF;
#pragma unroll
            for (int i = 0; i < 4; i++) {
                int p = lane + 32 * i;
                if (p >= s && p < e) {
                    int pk = (dfv[i] << 7) | p;
                    if (pk < best) best = pk;
                }
            }
#pragma unroll
            for (int o = 16; o; o >>= 1) {
                int ot = __shfl_xor_sync(0xffffffffu, best, o);
                if (ot < best) best = ot;
            }
            return best & 127;
        };

        int nn = 0, root;
        if (n <= 0) root = REF_NONE;
        else if (n == 1) root = REF_LEAF | 0;
        else {
            int sp = 0;
            ss[0] = 0; se[0] = (short)n; sst[0] = 0; sp = 1;
            int ret = 0;
            bool returning = false;
            while (sp > 0) {
                int top = sp - 1;
                if (returning) {
                    if (sst[top] == 1) {
                        sleft[top] = ret; sst[top] = 2; returning = false;
                    } else {
                        int Lr = sleft[top], Rr = ret, x = spos[top];
                        int ll = (Lr >= 0 && !(Lr & REF_LEAF)) ? lvl[Lr] : 0;
                        int rl = (Rr >= 0 && !(Rr & REF_LEAF)) ? lvl[Rr] : 0;
                        lvl[nn] = 1 + (ll > rl ? ll : rl);
                        if (lane == 0) {
                            g_nodeL[b * 128 + nn] = Lr;
                            g_nodeR[b * 128 + nn] = Rr;
                            g_nodeX[b * 128 + nn] = x;
                            g_nodeLvl[b * 128 + nn] = lvl[nn];
                        }
                        ret = nn; nn++; sp--;
                        continue;
                    }
                }
                if (sst[top] == 0) {
                    int s = ss[top], e = se[top];
                    int bp = argminSeg(s, e);
                    spos[top] = (short)bp;
                    if (bp == s)          { sleft[top] = REF_NONE;     sst[top] = 2; }
                    else if (bp == s + 1) { sleft[top] = REF_LEAF | s; sst[top] = 2; }
                    else {
                        sst[top] = 1;
                        ss[sp] = (short)s; se[sp] = (short)bp; sst[sp] = 0; sp++;
                        continue;
                    }
                }
                if (sst[top] == 2) {
                    int rs = spos[top] + 1, e = se[top];
                    int Rr;
                    if (rs == e)          Rr = REF_NONE;
                    else if (rs + 1 == e) Rr = REF_LEAF | rs;
                    else {
                        sst[top] = 3;
                        ss[sp] = (short)rs; se[sp] = (short)e; sst[sp] = 0; sp++;
                        continue;
                    }
                    int Lr = sleft[top], x = spos[top];
                    int ll = (Lr >= 0 && !(Lr & REF_LEAF)) ? lvl[Lr] : 0;
                    int rl = (Rr >= 0 && !(Rr & REF_LEAF)) ? lvl[Rr] : 0;
                    lvl[nn] = 1 + (ll > rl ? ll : rl);
                    if (lane == 0) {
                        g_nodeL[b * 128 + nn] = Lr;
                        g_nodeR[b * 128 + nn] = Rr;
                        g_nodeX[b * 128 + nn] = x;
                        g_nodeLvl[b * 128 + nn] = lvl[nn];
                    }
                    ret = nn; nn++; sp--;
                    returning = true;
                }
            }
            root = ret;
        }
        if (lane == 0) { g_root[b] = root; g_nNodes[b] = nn; }
    }
    __syncthreads();
    if (threadIdx.x == 0) {
        int cnt[130];
        for (int i = 0; i < 130; i++) cnt[i] = 0;
        int mx = 0;
        for (int bb = 0; bb < kB; bb++) {
            int nn = g_nNodes[bb];
            for (int i = 0; i < nn; i++) {
                int lv = g_nodeLvl[bb * 128 + i];
                cnt[lv]++;
                if (lv > mx) mx = lv;
            }
        }
        int run = 0;
        for (int lv = 1; lv <= mx; lv++) { g_lvlOff[lv] = run; run += cnt[lv]; }
        g_lvlOff[mx + 1] = run;
        int pos[130];
        for (int lv = 1; lv <= mx; lv++) pos[lv] = g_lvlOff[lv];
        for (int bb = 0; bb < kB; bb++) {
            int nn = g_nNodes[bb];
            for (int i = 0; i < nn; i++) {
                int lv = g_nodeLvl[bb * 128 + i];
                g_lvlList[pos[lv]++] = (bb << 8) | i;
            }
        }
        g_maxLvl = mx;
    }
}

// ---------------- X precompute: g_X = emb @ W_ih^T + b_ih + b_hh ----------------
__global__ __launch_bounds__(256, 3) void x_kernel(const float *__restrict__ emb,
                                                   const float *__restrict__ Wih,
                                                   const float *__restrict__ bih,
                                                   const float *__restrict__ bhh) {
    extern __shared__ float xsm[];
    gemm2<64, false>(emb, kD, kB * kL, 0, Wih, kD, kH4, kD, 1, 0,
                     g_X, kH4, bih, bhh, xsm);
}

// ---------------- LSTM kernel (weight-stationary, deep LDG pipeline) ----------------
__global__ __launch_bounds__(256, 1) void lstm_kernel(const float *__restrict__ Whh) {
    extern __shared__ float sm[];
    unsigned gen = *((volatile unsigned *)&g_barGen);
    const int tid = threadIdx.x;
    const int bk = blockIdx.x;

    int nj = 1024 - bk * 7;
    if (nj > 7) nj = 7;
    if (nj < 0) nj = 0;
    for (int idx = tid; idx < nj * 4096; idx += 256)
        sm[idx] = __ldg(&Whh[((size_t)((idx >> 10) & 3) * kH + bk * 7 + (idx >> 12)) * kH
                             + (idx & 1023)]);
    __syncthreads();

    const int s = tid >> 5, b = tid & 31;
    const bool active = (s < nj);
    const int j = bk * 7 + s;
    const float *Ws = sm + s * 4096;
    float cprev = 0.0f;

    for (int t = 0; t < kL; t++) {
        float av[4] = {0.f, 0.f, 0.f, 0.f};
        if (active) {
            if (t > 0) {
                u64 accp[4] = {0ULL, 0ULL, 0ULL, 0ULL};
                const float *hTp = (const float *)g_hT[(t - 1) & 1];
#pragma unroll 16
                for (int kq = 0; kq < 256; kq++) {
                    float4 h4 = __ldcg((const float4 *)(hTp + kq * 128 + b * 4));
                    u64 alo = pack2(h4.x, h4.y);
                    u64 ahi = pack2(h4.z, h4.w);
#pragma unroll
                    for (int g = 0; g < 4; g++) {
                        ulonglong2 w = *(const ulonglong2 *)(Ws + g * 1024 + kq * 4);
                        ffma2(accp[g], alo, w.x);
                        ffma2(accp[g], ahi, w.y);
                    }
                }
#pragma unroll
                for (int g = 0; g < 4; g++) {
                    float x, y; unpack2(accp[g], x, y);
                    av[g] = x + y;
                }
            }
            const float *Xr = g_X + ((size_t)(b * kL + t)) * kH4;
            float gi = av[0] + __ldg(Xr + j);
            float gf = av[1] + __ldg(Xr + kH + j);
            float gg = av[2] + __ldg(Xr + 2 * kH + j);
            float go = av[3] + __ldg(Xr + 3 * kH + j);
            float c = sigm(gf) * cprev + sigm(gi) * tanhf(gg);
            float h = sigm(go) * tanhf(c);
            cprev = c;
            __stcg(&g_hs[((size_t)(b * kL + t)) * kH + j], h);
            __stcg(&g_cs[((size_t)(b * kL + t)) * kH + j], c);
            __stcg(&g_hT[t & 1][(j >> 2) * 128 + b * 4 + (j & 3)], h);
        }
        gridBarrier(gen);
    }
}

// ---------------- compose kernel: 444 persistent blocks, 3/SM ----------------
__global__ __launch_bounds__(256, 3) void compose_kernel(const float *__restrict__ Wcomp,
                                                         const float *__restrict__ bcomp,
                                                         float *__restrict__ out) {
    extern __shared__ float sm[];
    unsigned gen = *((volatile unsigned *)&g_barGen);
    const int tid = threadIdx.x;
    const int gtid = blockIdx.x * 256 + tid;
    const int gsz = gridDim.x * 256;
    const int maxLvl = g_maxLvl;

    for (int lvl = 1; lvl <= maxLvl; lvl++) {
        const int off = g_lvlOff[lvl];
        const int cnt = g_lvlOff[lvl + 1] - off;
        // per-ksplit non-overlapping partial stride: (MAXM/ksplit) rows each.
        // ks2 -> 1024 rows (cnt<=384), ks4 -> 512 (cnt<=128), ks8 -> 256 (cnt<=32).
        int ksplit;
        if (cnt > 384)       ksplit = 1;
        else if (cnt > 128)  ksplit = 2;
        else if (cnt > 32)   ksplit = 4;
        else                 ksplit = 8;
        const size_t partStride = (size_t)(MAXM / ksplit) * kH6;

        if (ksplit == 8)
            gemm2<32, true>(nullptr, 0, cnt, off, Wcomp, kH3, kH6, kH3,
                            8, partStride, g_gates, kH6, nullptr, nullptr, sm);
        else if (ksplit == 4)
            gemm2<64, true>(nullptr, 0, cnt, off, Wcomp, kH3, kH6, kH3,
                            4, partStride, g_gates, kH6, nullptr, nullptr, sm);
        else if (ksplit == 2)
            gemm2<64, true>(nullptr, 0, cnt, off, Wcomp, kH3, kH6, kH3,
                            2, partStride, g_gates, kH6, nullptr, nullptr, sm);
        else
            gemm2<64, true>(nullptr, 0, cnt, off, Wcomp, kH3, kH6, kH3,
                            1, partStride, g_gates, kH6, nullptr, nullptr, sm);
        gridBarrier(gen);

        // epilogue: sum K-split partials + bias, gate nonlinearity, cell update
        for (int idx = gtid; idx < cnt * kH; idx += gsz) {
            int i = idx >> 10, jj = idx & 1023;
            int e = g_lvlList[off + i];
            int bb = e >> 8, nd = e & 255;
            const float *gp = g_gates + (size_t)i * kH6 + jj;
            float a0 = __ldg(bcomp + jj);
            float a1 = __ldg(bcomp + kH + jj);
            float a2 = __ldg(bcomp + 2 * kH + jj);
            float a3 = __ldg(bcomp + 3 * kH + jj);
            float a4 = __ldg(bcomp + 4 * kH + jj);
            float a5 = __ldg(bcomp + 5 * kH + jj);
            for (int p = 0; p < ksplit; p++) {
                const float *pp = gp + (size_t)p * partStride;
                a0 += __ldcg(pp);
                a1 += __ldcg(pp + kH);
                a2 += __ldcg(pp + 2 * kH);
                a3 += __ldcg(pp + 3 * kH);
                a4 += __ldcg(pp + 4 * kH);
                a5 += __ldcg(pp + 5 * kH);
            }
            int rl = g_nodeL[bb * 128 + nd];
            int rr = g_nodeR[bb * 128 + nd];
            int x  = g_nodeX[bb * 128 + nd];
            float cl = c_ofg(rl, bb, jj);
            float cr = c_ofg(rr, bb, jj);
            float cx = __ldg(&g_cs[(size_t)(bb * kL + x) * kH + jj]);
            float c = sigm(a0) * tanhf(a4) + sigm(a1) * cl + sigm(a2) * cx + sigm(a3) * cr;
            float h = sigm(a5) * tanhf(c);
            __stcg(&g_nodeh[(size_t)(bb * 128 + nd) * kH + jj], h);
            __stcg(&g_nodec[(size_t)(bb * 128 + nd) * kH + jj], c);
        }
        gridBarrier(gen);
    }

    // output: h then c of each batch root
    for (int idx = gtid; idx < kB * kH; idx += gsz) {
        int bb = idx >> 10, jj = idx & 1023;
        int r = g_root[bb];
        out[idx]           = h_ofg(r, bb, jj);
        out[kB * kH + idx] = c_ofg(r, bb, jj);
    }
}

// ---------------- launch ----------------
extern "C" void kernel_launch(void *const *d_in, const int *in_sizes, int n_in,
                              void *d_out, int out_size) {
    (void)in_sizes; (void)n_in; (void)out_size;
    const float *emb   = (const float *)d_in[0];
    const float *Wih   = (const float *)d_in[1];
    const float *Whh   = (const float *)d_in[2];
    const float *bih   = (const float *)d_in[3];
    const float *bhh   = (const float *)d_in[4];
    const float *Wcomp = (const float *)d_in[5];
    const float *bcomp = (const float *)d_in[6];
    const int *words   = (const int *)d_in[7];
    const int *len     = (const int *)d_in[8];
    float *out = (float *)d_out;

    // smem gemm2 BM=64: A 2*32*68*4=17408 + B 2*32*132*4=33792 + ptr 64*3*8=1536
    //   = 52736 B; 3 blocks/SM = 158.2 KB (< 228 KB); regs capped 80 by bounds.
    static bool attrDone = false;
    if (!attrDone) {
        cudaFuncSetAttribute(tree_kernel, cudaFuncAttributeMaxDynamicSharedMemorySize, 61440);
        cudaFuncSetAttribute(x_kernel, cudaFuncAttributeMaxDynamicSharedMemorySize, 52736);
        cudaFuncSetAttribute(lstm_kernel, cudaFuncAttributeMaxDynamicSharedMemorySize, 114688);
        cudaFuncSetAttribute(compose_kernel, cudaFuncAttributeMaxDynamicSharedMemorySize, 52736);
        attrDone = true;
    }

    tree_kernel<<<1, 1024, 61440>>>(words, len);
    x_kernel<<<2048, 256, 52736>>>(emb, Wih, bih, bhh);
    lstm_kernel<<<148, 256, 114688>>>(Whh);
    compose_kernel<<<444, 256, 52736>>>(Wcomp, bcomp, out);
}

// round 17
// speedup vs baseline: 1.2815x; 1.0207x over previous
#include <cuda_runtime.h>
#include <cuda_bf16.h>
#include <stdint.h>

constexpr int kB  = 32;
constexpr int kL  = 128;
constexpr int kD  = 300;
constexpr int kH  = 1024;
constexpr int kH3 = 3 * kH;
constexpr int kH4 = 4 * kH;
constexpr int kH6 = 6 * kH;
constexpr int MAXM = 2048;

#define REF_NONE  (-1)
#define REF_LEAF  0x40000000

typedef unsigned long long u64;

// ---------------- device scratch ----------------
__device__ float g_X[(size_t)kB * kL * kH4];
__device__ float g_hs[(size_t)kB * kL * kH];
__device__ float g_cs[(size_t)kB * kL * kH];
__device__ float g_nodeh[(size_t)kB * 128 * kH];
__device__ float g_nodec[(size_t)kB * 128 * kH];
__device__ float g_gates[(size_t)MAXM * kH6];     // also holds K-split partials
__device__ float g_hT[2][kH * kB];                // [(k>>2)*128 + b*4 + (k&3)]

__device__ int g_nodeL[kB * 128];
__device__ int g_nodeR[kB * 128];
__device__ int g_nodeX[kB * 128];
__device__ int g_nodeLvl[kB * 128];
__device__ int g_nNodes[kB];
__device__ int g_root[kB];
__device__ int g_lvlList[kB * 128];
__device__ int g_lvlOff[132];
__device__ int g_maxLvl;

__device__ unsigned g_barCount = 0;
__device__ unsigned g_barGen   = 0;

// ---------------- helpers ----------------
__device__ __forceinline__ float sigm(float x) { return 1.0f / (1.0f + expf(-x)); }

__device__ __forceinline__ void gridBarrier(unsigned &gen) {
    __syncthreads();
    if (threadIdx.x == 0) {
        __threadfence();
        if (atomicAdd(&g_barCount, 1u) == gridDim.x - 1u) {
            g_barCount = 0;
            __threadfence();
            atomicExch(&g_barGen, gen + 1u);
        } else {
            while (*((volatile unsigned *)&g_barGen) < gen + 1u) __nanosleep(32);
        }
    }
    gen++;
    __syncthreads();
}

__device__ __forceinline__ u64 packdup(float x) {
    u64 d; unsigned u = __float_as_uint(x);
    asm("mov.b64 %0, {%1, %1};" : "=l"(d) : "r"(u));
    return d;
}
__device__ __forceinline__ u64 pack2(float x, float y) {
    u64 d;
    asm("mov.b64 %0, {%1, %2};" : "=l"(d) : "r"(__float_as_uint(x)), "r"(__float_as_uint(y)));
    return d;
}
__device__ __forceinline__ void unpack2(u64 d, float &x, float &y) {
    unsigned a, b;
    asm("mov.b64 {%0, %1}, %2;" : "=r"(a), "=r"(b) : "l"(d));
    x = __uint_as_float(a); y = __uint_as_float(b);
}
__device__ __forceinline__ void ffma2(u64 &d, u64 a, u64 b) {
    asm("fma.rn.f32x2 %0, %1, %2, %0;" : "+l"(d) : "l"(a), "l"(b));
}

// L1-safe reads (each node h/c written exactly once, first read strictly after)
__device__ __forceinline__ float h_ofg(int ref, int b, int jj) {
    if (ref < 0) return 0.0f;
    if (ref & REF_LEAF) return __ldg(&g_hs[((size_t)(b * kL + (ref & 0xFFFF))) * kH + jj]);
    return __ldg(&g_nodeh[((size_t)(b * 128 + ref)) * kH + jj]);
}
__device__ __forceinline__ float c_ofg(int ref, int b, int jj) {
    if (ref < 0) return 0.0f;
    if (ref & REF_LEAF) return __ldg(&g_cs[((size_t)(b * kL + (ref & 0xFFFF))) * kH + jj]);
    return __ldg(&g_nodec[((size_t)(b * 128 + ref)) * kH + jj]);
}

// ------------- f32x2 GEMM: C[M,N] = A(MxK) @ B(NxK)^T, optional K-split -------------
// 256 threads. BN=128, BK=32, thread tile TM x 8 with the 8 columns split as
// {tx*4..tx*4+3} and {64+tx*4..} -> conflict-free LDS.128 B reads (R12-proven loop).
// GATHER: per-tile row base-pointer table (rowPtr[BM][3]) built once per tile; per-chunk
// A load is a pure float4 LDG (R15-proven). NEW (R16): B loads are float4 (4x LDG.128
// per thread per chunk instead of 16 scalar LDG), scattered to 4 kk rows at store.
// K-split: tile index selects ks; partial outputs at C + ks*partStride.
// CALLER guarantees partStride rows >= max cnt for the ksplit tier, and that kBase/k0
// are multiples of 4 with 16B-aligned rows (holds: ldb in {3072,300,1024}, K mult of 4).
template <int BM, bool GATHER>
__device__ void gemm2(const float *__restrict__ A, int lda, int M, int lvlOff,
                      const float *__restrict__ Bw, int ldb, int N, int K,
                      int ksplit, size_t partStride,
                      float *__restrict__ C, int ldc,
                      const float *__restrict__ bias1,
                      const float *__restrict__ bias2, float *sm) {
    constexpr int BK = 32, BN = 128, TN = 8;
    constexpr int TM = BM / 16;
    constexpr int NP = TM / 2;
    constexpr int ALD = BM + 4;
    float *As = sm;                          // [2][BK][ALD]
    float *Bs = sm + 2 * BK * ALD;           // [2][BK][132]
    u64 *rowPtr = (u64 *)(sm + 2 * BK * ALD + 2 * BK * 132);  // [BM][3]
    const int tid = threadIdx.x;
    const int ty = tid >> 4, tx = tid & 15;
    const int tilesM = (M + BM - 1) / BM;
    const int tilesN = N / BN;
    const int tilesMN = tilesM * tilesN;
    const int kLen = K / ksplit;
    const int nk = (kLen + BK - 1) / BK;
    const int total = tilesMN * ksplit;

    for (int t = blockIdx.x; t < total; t += gridDim.x) {
        const int ks = t / tilesMN;
        const int tmn = t - ks * tilesMN;
        const int tm = tmn % tilesM, tn = tmn / tilesM;
        const int m0 = tm * BM, n0 = tn * BN;
        const int kBase = ks * kLen;
        const int kEnd = (kBase + kLen < K) ? (kBase + kLen) : K;
        float *Cp = C + (size_t)ks * partStride;
        u64 acc[NP][TN];
#pragma unroll
        for (int p = 0; p < NP; p++)
#pragma unroll
            for (int j = 0; j < TN; j++) acc[p][j] = 0ULL;

        if (GATHER) {
            // build per-row segment base pointers once per tile
            for (int idx = tid; idx < BM * 3; idx += 256) {
                int m = idx / 3, seg = idx - m * 3;
                int row = m0 + m;
                u64 p = 0;
                if (row < M) {
                    int e = __ldg(&g_lvlList[lvlOff + row]);
                    int bb = e >> 8, nd = e & 255;
                    if (seg == 1) {
                        int x = __ldg(&g_nodeX[bb * 128 + nd]);
                        p = (u64)(uintptr_t)&g_hs[(size_t)(bb * kL + x) * kH];
                    } else {
                        int ref = __ldg(seg == 0 ? &g_nodeL[bb * 128 + nd]
                                                 : &g_nodeR[bb * 128 + nd]);
                        if (ref >= 0) {
                            p = (ref & REF_LEAF)
                                ? (u64)(uintptr_t)&g_hs[(size_t)(bb * kL + (ref & 0xFFFF)) * kH]
                                : (u64)(uintptr_t)&g_nodeh[(size_t)(bb * 128 + ref) * kH];
                        }
                    }
                }
                rowPtr[idx] = p;
            }
            __syncthreads();
        }

        auto load = [&](int buf, int k0) {
            // A: float4 per thread (gather via precomputed pointers, or dense)
#pragma unroll
            for (int i = 0; i < BM / 32; i++) {
                int idx = tid + i * 256;
                int kq = idx & 7, m = idx >> 3;
                int k = kBase + k0 + kq * 4;
                float4 v = make_float4(0.f, 0.f, 0.f, 0.f);
                if (GATHER) {
                    int seg = k >> 10;
                    const float *p = (const float *)(uintptr_t)rowPtr[m * 3 + seg];
                    if (p && k < kEnd)
                        v = __ldg((const float4 *)(p + (k & 1023)));
                } else {
                    int row = m0 + m;
                    if (row < M && k < kEnd)
                        v = __ldg((const float4 *)(A + (size_t)row * lda + k));
                }
                float *dst = &As[(buf * BK + kq * 4) * ALD + m];
                dst[0]       = v.x;
                dst[ALD]     = v.y;
                dst[2 * ALD] = v.z;
                dst[3 * ALD] = v.w;
            }
            // B: float4 per thread, scatter to 4 kk rows
#pragma unroll
            for (int i = 0; i < 4; i++) {
                int idx = tid + i * 256;
                int kq = idx & 7, n = idx >> 3;
                int k = kBase + k0 + kq * 4;
                float4 v = make_float4(0.f, 0.f, 0.f, 0.f);
                if (k < kEnd)
                    v = __ldg((const float4 *)(Bw + (size_t)(n0 + n) * ldb + k));
                float *dst = &Bs[(buf * BK + kq * 4) * 132 + n];
                dst[0]       = v.x;
                dst[132]     = v.y;
                dst[2 * 132] = v.z;
                dst[3 * 132] = v.w;
            }
        };

        load(0, 0);
        __syncthreads();
        for (int kt = 0; kt < nk; kt++) {
            int buf = kt & 1;
            if (kt + 1 < nk) load(buf ^ 1, (kt + 1) * BK);
#pragma unroll
            for (int kk = 0; kk < BK; kk++) {
                const float *Ar = &As[(buf * BK + kk) * ALD + ty * TM];
                u64 a2[NP];
                if constexpr (NP == 4) {
                    ulonglong2 t0 = *(const ulonglong2 *)Ar;
                    ulonglong2 t1 = *(const ulonglong2 *)(Ar + 4);
                    a2[0] = t0.x; a2[1] = t0.y; a2[2] = t1.x; a2[3] = t1.y;
                } else if constexpr (NP == 2) {
                    ulonglong2 t0 = *(const ulonglong2 *)Ar;
                    a2[0] = t0.x; a2[1] = t0.y;
                } else {
                    a2[0] = *(const u64 *)Ar;
                }
                // conflict-free B reads: stride-4-word addresses per lane
                const float *Brow = &Bs[(buf * BK + kk) * 132];
                float4 b0 = *(const float4 *)(Brow + tx * 4);
                float4 b1 = *(const float4 *)(Brow + 64 + tx * 4);
                u64 bd[8];
                bd[0] = packdup(b0.x); bd[1] = packdup(b0.y);
                bd[2] = packdup(b0.z); bd[3] = packdup(b0.w);
                bd[4] = packdup(b1.x); bd[5] = packdup(b1.y);
                bd[6] = packdup(b1.z); bd[7] = packdup(b1.w);
#pragma unroll
                for (int p = 0; p < NP; p++)
#pragma unroll
                    for (int j = 0; j < TN; j++) ffma2(acc[p][j], a2[p], bd[j]);
            }
            __syncthreads();
        }
#pragma unroll
        for (int p = 0; p < NP; p++) {
            int r = m0 + ty * TM + 2 * p;
#pragma unroll
            for (int j = 0; j < TN; j++) {
                float x, y; unpack2(acc[p][j], x, y);
                int col = n0 + ((j < 4) ? (tx * 4 + j) : (64 + tx * 4 + (j - 4)));
                float bv = 0.0f;
                if (bias1) bv += __ldg(bias1 + col);
                if (bias2) bv += __ldg(bias2 + col);
                if (r < M)     __stcg(Cp + (size_t)r * ldc + col, x + bv);
                if (r + 1 < M) __stcg(Cp + (size_t)(r + 1) * ldc + col, y + bv);
            }
        }
        if (GATHER) __syncthreads();   // protect rowPtr before next tile rewrites it
    }
}

// ---------------- tree kernel: warp per batch, stacks in smem ----------------
__global__ __launch_bounds__(1024) void tree_kernel(const int *__restrict__ words,
                                                    const int *__restrict__ length) {
    extern __shared__ char tsm[];
    int wid = threadIdx.x >> 5, lane = threadIdx.x & 31;
    if (wid < kB) {
        int b = wid;
        char *wb = tsm + wid * 1920;
        short *ss   = (short *)(wb);
        short *se   = (short *)(wb + 256);
        short *spos = (short *)(wb + 512);
        signed char *sst = (signed char *)(wb + 768);
        int *sleft  = (int *)(wb + 896);
        int *lvl    = (int *)(wb + 1408);

        int dfv[4];
#pragma unroll
        for (int i = 0; i < 4; i++) dfv[i] = words[b * kL + lane + 32 * i] % 1000;
        int n = length[b];

        auto argminSeg = [&](int s, int e) -> int {
            int best = 0x7FFFFFFF;
#pragma unroll
            for (int i = 0; i < 4; i++) {
                int p = lane + 32 * i;
                if (p >= s && p < e) {
                    int pk = (dfv[i] << 7) | p;
                    if (pk < best) best = pk;
                }
            }
#pragma unroll
            for (int o = 16; o; o >>= 1) {
                int ot = __shfl_xor_sync(0xffffffffu, best, o);
                if (ot < best) best = ot;
            }
            return best & 127;
        };

        int nn = 0, root;
        if (n <= 0) root = REF_NONE;
        else if (n == 1) root = REF_LEAF | 0;
        else {
            int sp = 0;
            ss[0] = 0; se[0] = (short)n; sst[0] = 0; sp = 1;
            int ret = 0;
            bool returning = false;
            while (sp > 0) {
                int top = sp - 1;
                if (returning) {
                    if (sst[top] == 1) {
                        sleft[top] = ret; sst[top] = 2; returning = false;
                    } else {
                        int Lr = sleft[top], Rr = ret, x = spos[top];
                        int ll = (Lr >= 0 && !(Lr & REF_LEAF)) ? lvl[Lr] : 0;
                        int rl = (Rr >= 0 && !(Rr & REF_LEAF)) ? lvl[Rr] : 0;
                        lvl[nn] = 1 + (ll > rl ? ll : rl);
                        if (lane == 0) {
                            g_nodeL[b * 128 + nn] = Lr;
                            g_nodeR[b * 128 + nn] = Rr;
                            g_nodeX[b * 128 + nn] = x;
                            g_nodeLvl[b * 128 + nn] = lvl[nn];
                        }
                        ret = nn; nn++; sp--;
                        continue;
                    }
                }
                if (sst[top] == 0) {
                    int s = ss[top], e = se[top];
                    int bp = argminSeg(s, e);
                    spos[top] = (short)bp;
                    if (bp == s)          { sleft[top] = REF_NONE;     sst[top] = 2; }
                    else if (bp == s + 1) { sleft[top] = REF_LEAF | s; sst[top] = 2; }
                    else {
                        sst[top] = 1;
                        ss[sp] = (short)s; se[sp] = (short)bp; sst[sp] = 0; sp++;
                        continue;
                    }
                }
                if (sst[top] == 2) {
                    int rs = spos[top] + 1, e = se[top];
                    int Rr;
                    if (rs == e)          Rr = REF_NONE;
                    else if (rs + 1 == e) Rr = REF_LEAF | rs;
                    else {
                        sst[top] = 3;
                        ss[sp] = (short)rs; se[sp] = (short)e; sst[sp] = 0; sp++;
                        continue;
                    }
                    int Lr = sleft[top], x = spos[top];
                    int ll = (Lr >= 0 && !(Lr & REF_LEAF)) ? lvl[Lr] : 0;
                    int rl = (Rr >= 0 && !(Rr & REF_LEAF)) ? lvl[Rr] : 0;
                    lvl[nn] = 1 + (ll > rl ? ll : rl);
                    if (lane == 0) {
                        g_nodeL[b * 128 + nn] = Lr;
                        g_nodeR[b * 128 + nn] = Rr;
                        g_nodeX[b * 128 + nn] = x;
                        g_nodeLvl[b * 128 + nn] = lvl[nn];
                    }
                    ret = nn; nn++; sp--;
                    returning = true;
                }
            }
            root = ret;
        }
        if (lane == 0) { g_root[b] = root; g_nNodes[b] = nn; }
    }
    __syncthreads();
    if (threadIdx.x == 0) {
        int cnt[130];
        for (int i = 0; i < 130; i++) cnt[i] = 0;
        int mx = 0;
        for (int bb = 0; bb < kB; bb++) {
            int nn = g_nNodes[bb];
            for (int i = 0; i < nn; i++) {
                int lv = g_nodeLvl[bb * 128 + i];
                cnt[lv]++;
                if (lv > mx) mx = lv;
            }
        }
        int run = 0;
        for (int lv = 1; lv <= mx; lv++) { g_lvlOff[lv] = run; run += cnt[lv]; }
        g_lvlOff[mx + 1] = run;
        int pos[130];
        for (int lv = 1; lv <= mx; lv++) pos[lv] = g_lvlOff[lv];
        for (int bb = 0; bb < kB; bb++) {
            int nn = g_nNodes[bb];
            for (int i = 0; i < nn; i++) {
                int lv = g_nodeLvl[bb * 128 + i];
                g_lvlList[pos[lv]++] = (bb << 8) | i;
            }
        }
        g_maxLvl = mx;
    }
}

// ---------------- X precompute: g_X = emb @ W_ih^T + b_ih + b_hh ----------------
__global__ __launch_bounds__(256, 3) void x_kernel(const float *__restrict__ emb,
                                                   const float *__restrict__ Wih,
                                                   const float *__restrict__ bih,
                                                   const float *__restrict__ bhh) {
    extern __shared__ float xsm[];
    gemm2<64, false>(emb, kD, kB * kL, 0, Wih, kD, kH4, kD, 1, 0,
                     g_X, kH4, bih, bhh, xsm);
}

// ---------------- LSTM kernel (weight-stationary, deep LDG pipeline) ----------------
__global__ __launch_bounds__(256, 1) void lstm_kernel(const float *__restrict__ Whh) {
    extern __shared__ float sm[];
    unsigned gen = *((volatile unsigned *)&g_barGen);
    const int tid = threadIdx.x;
    const int bk = blockIdx.x;

    int nj = 1024 - bk * 7;
    if (nj > 7) nj = 7;
    if (nj < 0) nj = 0;
    for (int idx = tid; idx < nj * 4096; idx += 256)
        sm[idx] = __ldg(&Whh[((size_t)((idx >> 10) & 3) * kH + bk * 7 + (idx >> 12)) * kH
                             + (idx & 1023)]);
    __syncthreads();

    const int s = tid >> 5, b = tid & 31;
    const bool active = (s < nj);
    const int j = bk * 7 + s;
    const float *Ws = sm + s * 4096;
    float cprev = 0.0f;

    for (int t = 0; t < kL; t++) {
        float av[4] = {0.f, 0.f, 0.f, 0.f};
        if (active) {
            if (t > 0) {
                u64 accp[4] = {0ULL, 0ULL, 0ULL, 0ULL};
                const float *hTp = (const float *)g_hT[(t - 1) & 1];
#pragma unroll 16
                for (int kq = 0; kq < 256; kq++) {
                    float4 h4 = __ldcg((const float4 *)(hTp + kq * 128 + b * 4));
                    u64 alo = pack2(h4.x, h4.y);
                    u64 ahi = pack2(h4.z, h4.w);
#pragma unroll
                    for (int g = 0; g < 4; g++) {
                        ulonglong2 w = *(const ulonglong2 *)(Ws + g * 1024 + kq * 4);
                        ffma2(accp[g], alo, w.x);
                        ffma2(accp[g], ahi, w.y);
                    }
                }
#pragma unroll
                for (int g = 0; g < 4; g++) {
                    float x, y; unpack2(accp[g], x, y);
                    av[g] = x + y;
                }
            }
            const float *Xr = g_X + ((size_t)(b * kL + t)) * kH4;
            float gi = av[0] + __ldg(Xr + j);
            float gf = av[1] + __ldg(Xr + kH + j);
            float gg = av[2] + __ldg(Xr + 2 * kH + j);
            float go = av[3] + __ldg(Xr + 3 * kH + j);
            float c = sigm(gf) * cprev + sigm(gi) * tanhf(gg);
            float h = sigm(go) * tanhf(c);
            cprev = c;
            __stcg(&g_hs[((size_t)(b * kL + t)) * kH + j], h);
            __stcg(&g_cs[((size_t)(b * kL + t)) * kH + j], c);
            __stcg(&g_hT[t & 1][(j >> 2) * 128 + b * 4 + (j & 3)], h);
        }
        gridBarrier(gen);
    }
}

// ---------------- compose kernel: 444 persistent blocks, 3/SM ----------------
__global__ __launch_bounds__(256, 3) void compose_kernel(const float *__restrict__ Wcomp,
                                                         const float *__restrict__ bcomp,
                                                         float *__restrict__ out) {
    extern __shared__ float sm[];
    unsigned gen = *((volatile unsigned *)&g_barGen);
    const int tid = threadIdx.x;
    const int gtid = blockIdx.x * 256 + tid;
    const int gsz = gridDim.x * 256;
    const int maxLvl = g_maxLvl;

    for (int lvl = 1; lvl <= maxLvl; lvl++) {
        const int off = g_lvlOff[lvl];
        const int cnt = g_lvlOff[lvl + 1] - off;
        // per-ksplit non-overlapping partial stride: (MAXM/ksplit) rows each.
        // ks2 -> 1024 rows (cnt<=384), ks4 -> 512 (cnt<=128), ks8 -> 256 (cnt<=32).
        int ksplit;
        if (cnt > 384)       ksplit = 1;
        else if (cnt > 128)  ksplit = 2;
        else if (cnt > 32)   ksplit = 4;
        else                 ksplit = 8;
        const size_t partStride = (size_t)(MAXM / ksplit) * kH6;

        if (ksplit == 8)
            gemm2<32, true>(nullptr, 0, cnt, off, Wcomp, kH3, kH6, kH3,
                            8, partStride, g_gates, kH6, nullptr, nullptr, sm);
        else if (ksplit == 4)
            gemm2<64, true>(nullptr, 0, cnt, off, Wcomp, kH3, kH6, kH3,
                            4, partStride, g_gates, kH6, nullptr, nullptr, sm);
        else if (ksplit == 2)
            gemm2<64, true>(nullptr, 0, cnt, off, Wcomp, kH3, kH6, kH3,
                            2, partStride, g_gates, kH6, nullptr, nullptr, sm);
        else
            gemm2<64, true>(nullptr, 0, cnt, off, Wcomp, kH3, kH6, kH3,
                            1, partStride, g_gates, kH6, nullptr, nullptr, sm);
        gridBarrier(gen);

        // epilogue: sum K-split partials + bias, gate nonlinearity, cell update
        for (int idx = gtid; idx < cnt * kH; idx += gsz) {
            int i = idx >> 10, jj = idx & 1023;
            int e = g_lvlList[off + i];
            int bb = e >> 8, nd = e & 255;
            const float *gp = g_gates + (size_t)i * kH6 + jj;
            float a0 = __ldg(bcomp + jj);
            float a1 = __ldg(bcomp + kH + jj);
            float a2 = __ldg(bcomp + 2 * kH + jj);
            float a3 = __ldg(bcomp + 3 * kH + jj);
            float a4 = __ldg(bcomp + 4 * kH + jj);
            float a5 = __ldg(bcomp + 5 * kH + jj);
            for (int p = 0; p < ksplit; p++) {
                const float *pp = gp + (size_t)p * partStride;
                a0 += __ldcg(pp);
                a1 += __ldcg(pp + kH);
                a2 += __ldcg(pp + 2 * kH);
                a3 += __ldcg(pp + 3 * kH);
                a4 += __ldcg(pp + 4 * kH);
                a5 += __ldcg(pp + 5 * kH);
            }
            int rl = g_nodeL[bb * 128 + nd];
            int rr = g_nodeR[bb * 128 + nd];
            int x  = g_nodeX[bb * 128 + nd];
            float cl = c_ofg(rl, bb, jj);
            float cr = c_ofg(rr, bb, jj);
            float cx = __ldg(&g_cs[(size_t)(bb * kL + x) * kH + jj]);
            float c = sigm(a0) * tanhf(a4) + sigm(a1) * cl + sigm(a2) * cx + sigm(a3) * cr;
            float h = sigm(a5) * tanhf(c);
            __stcg(&g_nodeh[(size_t)(bb * 128 + nd) * kH + jj], h);
            __stcg(&g_nodec[(size_t)(bb * 128 + nd) * kH + jj], c);
        }
        gridBarrier(gen);
    }

    // output: h then c of each batch root
    for (int idx = gtid; idx < kB * kH; idx += gsz) {
        int bb = idx >> 10, jj = idx & 1023;
        int r = g_root[bb];
        out[idx]           = h_ofg(r, bb, jj);
        out[kB * kH + idx] = c_ofg(r, bb, jj);
    }
}

// ---------------- launch ----------------
extern "C" void kernel_launch(void *const *d_in, const int *in_sizes, int n_in,
                              void *d_out, int out_size) {
    (void)in_sizes; (void)n_in; (void)out_size;
    const float *emb   = (const float *)d_in[0];
    const float *Wih   = (const float *)d_in[1];
    const float *Whh   = (const float *)d_in[2];
    const float *bih   = (const float *)d_in[3];
    const float *bhh   = (const float *)d_in[4];
    const float *Wcomp = (const float *)d_in[5];
    const float *bcomp = (const float *)d_in[6];
    const int *words   = (const int *)d_in[7];
    const int *len     = (const int *)d_in[8];
    float *out = (float *)d_out;

    // smem gemm2 BM=64: A 2*32*68*4=17408 + B 2*32*132*4=33792 + ptr 64*3*8=1536
    //   = 52736 B; 3 blocks/SM = 158.2 KB (< 228 KB); regs capped 80 by bounds.
    static bool attrDone = false;
    if (!attrDone) {
        cudaFuncSetAttribute(tree_kernel, cudaFuncAttributeMaxDynamicSharedMemorySize, 61440);
        cudaFuncSetAttribute(x_kernel, cudaFuncAttributeMaxDynamicSharedMemorySize, 52736);
        cudaFuncSetAttribute(lstm_kernel, cudaFuncAttributeMaxDynamicSharedMemorySize, 114688);
        cudaFuncSetAttribute(compose_kernel, cudaFuncAttributeMaxDynamicSharedMemorySize, 52736);
        attrDone = true;
    }

    tree_kernel<<<1, 1024, 61440>>>(words, len);
    x_kernel<<<2048, 256, 52736>>>(emb, Wih, bih, bhh);
    lstm_kernel<<<148, 256, 114688>>>(Whh);
    compose_kernel<<<444, 256, 52736>>>(Wcomp, bcomp, out);
}